// round 5
// baseline (speedup 1.0000x reference)
#include <cuda_runtime.h>
#include <cuda_bf16.h>
#include <cstdint>
#include <cstddef>

#define BB 2
#define HH 12
#define SS 2048
#define DD 64
#define MT 128              // q rows per block
#define NK 128              // keys per chunk
#define NCH (SS/NK)         // 16
#define THREADS 512

// ---- smem byte offsets: double-buffered K/V hi/lo tiles ----
// buf b at b*65536: KHI +0, KLO +16384, VHI +32768, VLO +49152
#define SM_BUF0  0
#define SM_BUFSZ 65536
#define SM_BM    131072               // 2 bufs x 4 uint32 bitmasks
#define SM_RS    131104               // 2 x 128 floats (rowsum partials)
#define SM_TOTAL 132160
// out-reduction scratch (128x64 fp32 = 32KB) aliases buf0 (dead after c=14)

__device__ __forceinline__ uint32_t smem_u32(const void* p) {
    uint32_t a;
    asm("{ .reg .u64 t; cvta.to.shared.u64 t, %1; cvt.u32.u64 %0, t; }" : "=r"(a) : "l"(p));
    return a;
}
__device__ __forceinline__ uint32_t swz(int row, int ch) {
    return (uint32_t)(row * 128 + ((ch ^ (row & 7)) << 4));
}
__device__ __forceinline__ void ldmx4(uint32_t* r, uint32_t addr) {
    asm volatile("ldmatrix.sync.aligned.m8n8.x4.shared.b16 {%0,%1,%2,%3}, [%4];"
                 : "=r"(r[0]), "=r"(r[1]), "=r"(r[2]), "=r"(r[3]) : "r"(addr));
}
__device__ __forceinline__ void ldmx4t(uint32_t* r, uint32_t addr) {
    asm volatile("ldmatrix.sync.aligned.m8n8.x4.trans.shared.b16 {%0,%1,%2,%3}, [%4];"
                 : "=r"(r[0]), "=r"(r[1]), "=r"(r[2]), "=r"(r[3]) : "r"(addr));
}
__device__ __forceinline__ void mma16816(float* d, const uint32_t* a, const uint32_t* b) {
    asm volatile("mma.sync.aligned.m16n8k16.row.col.f32.bf16.bf16.f32 "
                 "{%0,%1,%2,%3}, {%4,%5,%6,%7}, {%8,%9}, {%0,%1,%2,%3};"
                 : "+f"(d[0]), "+f"(d[1]), "+f"(d[2]), "+f"(d[3])
                 : "r"(a[0]), "r"(a[1]), "r"(a[2]), "r"(a[3]), "r"(b[0]), "r"(b[1]));
}
__device__ __forceinline__ void cvt_split(float a, float b, uint32_t& hw, uint32_t& lw) {
    __nv_bfloat16 ha = __float2bfloat16(a), hb = __float2bfloat16(b);
    float ra = a - __bfloat162float(ha);
    float rb = b - __bfloat162float(hb);
    hw = ((uint32_t)__bfloat16_as_ushort(hb) << 16) | (uint32_t)__bfloat16_as_ushort(ha);
    __nv_bfloat16 la = __float2bfloat16(ra), lb = __float2bfloat16(rb);
    lw = ((uint32_t)__bfloat16_as_ushort(lb) << 16) | (uint32_t)__bfloat16_as_ushort(la);
}

extern __shared__ char smem[];

// LDG a [128][64] fp32 tile into 8 float2 regs (512-thread cooperative)
__device__ __forceinline__ void ldg_tile(const float* __restrict__ src, float2* r, int tid) {
    #pragma unroll
    for (int it = 0; it < 8; ++it) {
        int lin = it * THREADS + tid;
        int rr = lin >> 5, dp = lin & 31;
        r[it] = *(const float2*)(src + rr * DD + 2 * dp);
    }
}
// convert+store those regs into swizzled bf16 hi/lo tiles
__device__ __forceinline__ void sts_tile(const float2* r, char* hib, char* lob, int tid) {
    #pragma unroll
    for (int it = 0; it < 8; ++it) {
        int lin = it * THREADS + tid;
        int rr = lin >> 5, dp = lin & 31;
        uint32_t hw, lw;
        cvt_split(r[it].x, r[it].y, hw, lw);
        uint32_t off = (uint32_t)(rr * 128) + (((dp >> 2) ^ (rr & 7)) << 4) + ((dp & 3) << 2);
        *(uint32_t*)(hib + off) = hw;
        *(uint32_t*)(lob + off) = lw;
    }
}
__device__ __forceinline__ void stage_full(const float* __restrict__ src,
                                           char* hib, char* lob, float scale, int tid) {
    #pragma unroll
    for (int it = 0; it < 8; ++it) {
        int lin = it * THREADS + tid;
        int rr = lin >> 5, dp = lin & 31;
        float2 t = *(const float2*)(src + rr * DD + 2 * dp);
        uint32_t hw, lw;
        cvt_split(t.x * scale, t.y * scale, hw, lw);
        uint32_t off = (uint32_t)(rr * 128) + (((dp >> 2) ^ (rr & 7)) << 4) + ((dp & 3) << 2);
        *(uint32_t*)(hib + off) = hw;
        *(uint32_t*)(lob + off) = lw;
    }
}

__global__ __launch_bounds__(THREADS, 1)
void attn_hmma2_kernel(const float* __restrict__ q,
                       const float* __restrict__ k,
                       const float* __restrict__ v,
                       const int*   __restrict__ mask,
                       float* __restrict__ out,
                       float* __restrict__ probs)
{
    const uint32_t sbase = smem_u32(smem);
    const int tid = threadIdx.x;
    const int wid = tid >> 5;
    const int lid = tid & 31;
    const int qw  = wid >> 1;        // q-row tile 0..7 -> rows 16qw..16qw+15
    const int kh  = wid & 1;         // key half within chunk (0:keys 0-63, 1:64-127)
    const int grp = lid >> 3;
    const int lr  = lid & 7;
    const int q4  = lid & 3;
    const int r4  = lid >> 2;

    const int bh = blockIdx.y;
    const int b  = bh / HH;
    const int q0 = blockIdx.x * MT;
    const size_t bhrow = (size_t)bh * SS + q0;

    const float* qptr  = q + bhrow * DD;
    const float* kbase = k + (size_t)bh * SS * DD;
    const float* vbase = v + (size_t)bh * SS * DD;
    const int*   mbase = mask + b * SS;
    uint32_t* BMp = (uint32_t*)(smem + SM_BM);
    float*    rs  = (float*)(smem + SM_RS);

    // ---- stage Q (x0.125) into buf1 K region, load A-fragments ----
    stage_full(qptr, smem + SM_BUFSZ, smem + SM_BUFSZ + 16384, 0.125f, tid);
    __syncthreads();
    uint32_t qh[4][4], ql[4][4];
    {
        int row = 16 * qw + ((grp & 1) << 3) + lr;
        #pragma unroll
        for (int cc = 0; cc < 4; ++cc) {
            int ch = 2 * cc + (grp >> 1);
            ldmx4(qh[cc], sbase + SM_BUFSZ + swz(row, ch));
            ldmx4(ql[cc], sbase + SM_BUFSZ + 16384 + swz(row, ch));
        }
    }
    // ---- stage chunk 0 into buf0 + bitmask ----
    stage_full(kbase, smem + SM_BUF0,         smem + SM_BUF0 + 16384, 1.0f, tid);
    stage_full(vbase, smem + SM_BUF0 + 32768, smem + SM_BUF0 + 49152, 1.0f, tid);
    if (tid < NK) {
        uint32_t bal = __ballot_sync(0xFFFFFFFFu, mbase[tid] != 0);
        if ((tid & 31) == 0) BMp[tid >> 5] = bal;
    }
    __syncthreads();

    float oacc[8][4];
    #pragma unroll
    for (int n = 0; n < 8; ++n)
        #pragma unroll
        for (int i = 0; i < 4; ++i) oacc[n][i] = 0.0f;
    float rsum0 = 0.0f, rsum1 = 0.0f;

    for (int c = 0; c < NCH; ++c) {
        const uint32_t bufb = sbase + (uint32_t)(c & 1) * SM_BUFSZ;
        char* nb = smem + ((c + 1) & 1) * SM_BUFSZ;
        const bool more = (c + 1 < NCH);

        // issue next-K global loads (latency hidden behind QK)
        float2 rK[8];
        if (more) ldg_tile(kbase + (size_t)(c + 1) * NK * DD, rK, tid);

        // ---- QK^T: S[16 x 64] per warp (keys kh*64..), hi/lo split ----
        float sc[8][4];
        #pragma unroll
        for (int t = 0; t < 8; ++t)
            #pragma unroll
            for (int i = 0; i < 4; ++i) sc[t][i] = 0.0f;

        #pragma unroll
        for (int np = 0; np < 4; ++np) {
            int krow = kh * 64 + 16 * np + ((grp >> 1) << 3) + lr;
            #pragma unroll
            for (int cc = 0; cc < 4; ++cc) {
                int ch = 2 * cc + (grp & 1);
                uint32_t bhv[4], blv[4];
                ldmx4(bhv, bufb + swz(krow, ch));
                ldmx4(blv, bufb + 16384 + swz(krow, ch));
                mma16816(sc[2*np],   qh[cc], bhv + 0);
                mma16816(sc[2*np],   qh[cc], blv + 0);
                mma16816(sc[2*np],   ql[cc], bhv + 0);
                mma16816(sc[2*np+1], qh[cc], bhv + 2);
                mma16816(sc[2*np+1], qh[cc], blv + 2);
                mma16816(sc[2*np+1], ql[cc], bhv + 2);
            }
        }

        // store next-K to the other buffer (prev reads of it ended at last sync)
        if (more) sts_tile(rK, nb, nb + 16384, tid);
        // issue next-V global loads (latency hidden behind epilogue + PV)
        float2 rV[8];
        if (more) ldg_tile(vbase + (size_t)(c + 1) * NK * DD, rV, tid);

        // ---- epilogue: mask(bits) + exp, probs store, rowsum, pack A-frags ----
        const uint32_t bm0 = BMp[(c & 1) * 4 + kh * 2];
        const uint32_t bm1 = BMp[(c & 1) * 4 + kh * 2 + 1];
        float* prow = probs + (bhrow + 16 * qw + r4) * SS + c * NK + kh * 64;
        #pragma unroll
        for (int t = 0; t < 8; ++t) {
            int kl = 8 * t + 2 * q4;
            uint32_t bmw = (t < 4) ? bm0 : bm1;
            int sh = kl & 31;
            float p0 = ((bmw >> sh) & 1u)       ? __expf(sc[t][0]) : 0.0f;
            float p1 = ((bmw >> (sh + 1)) & 1u) ? __expf(sc[t][1]) : 0.0f;
            float p2 = ((bmw >> sh) & 1u)       ? __expf(sc[t][2]) : 0.0f;
            float p3 = ((bmw >> (sh + 1)) & 1u) ? __expf(sc[t][3]) : 0.0f;
            rsum0 += p0 + p1; rsum1 += p2 + p3;
            *(float2*)(prow + kl)          = make_float2(p0, p1);
            *(float2*)(prow + 8 * SS + kl) = make_float2(p2, p3);
            sc[t][0] = p0; sc[t][1] = p1; sc[t][2] = p2; sc[t][3] = p3;
        }
        uint32_t ahi[4][4], alo[4][4];
        #pragma unroll
        for (int j = 0; j < 4; ++j) {
            cvt_split(sc[2*j][0],   sc[2*j][1],   ahi[j][0], alo[j][0]);
            cvt_split(sc[2*j][2],   sc[2*j][3],   ahi[j][1], alo[j][1]);
            cvt_split(sc[2*j+1][0], sc[2*j+1][1], ahi[j][2], alo[j][2]);
            cvt_split(sc[2*j+1][2], sc[2*j+1][3], ahi[j][3], alo[j][3]);
        }

        // ---- PV: out[16 x 64] += P(kh half) . V, hi/lo split ----
        #pragma unroll
        for (int np = 0; np < 4; ++np) {
            int ch = 2 * np + (grp >> 1);
            #pragma unroll
            for (int j = 0; j < 4; ++j) {
                int vrow = kh * 64 + 16 * j + ((grp & 1) << 3) + lr;
                uint32_t vh[4], vl[4];
                ldmx4t(vh, bufb + 32768 + swz(vrow, ch));
                ldmx4t(vl, bufb + 49152 + swz(vrow, ch));
                mma16816(oacc[2*np],   ahi[j], vh + 0);
                mma16816(oacc[2*np],   ahi[j], vl + 0);
                mma16816(oacc[2*np],   alo[j], vh + 0);
                mma16816(oacc[2*np+1], ahi[j], vh + 2);
                mma16816(oacc[2*np+1], ahi[j], vl + 2);
                mma16816(oacc[2*np+1], alo[j], vh + 2);
            }
        }

        if (more) {
            sts_tile(rV, nb + 32768, nb + 49152, tid);
            if (tid < NK) {
                uint32_t bal = __ballot_sync(0xFFFFFFFFu, mbase[(c + 1) * NK + tid] != 0);
                if ((tid & 31) == 0) BMp[((c + 1) & 1) * 4 + (tid >> 5)] = bal;
            }
        }
        __syncthreads();
    }

    // ---- rowsum partials (quad-reduce, per key-half) ----
    rsum0 += __shfl_xor_sync(0xFFFFFFFFu, rsum0, 1);
    rsum0 += __shfl_xor_sync(0xFFFFFFFFu, rsum0, 2);
    rsum1 += __shfl_xor_sync(0xFFFFFFFFu, rsum1, 1);
    rsum1 += __shfl_xor_sync(0xFFFFFFFFu, rsum1, 2);
    if (q4 == 0) {
        rs[kh * 128 + 16 * qw + r4]     = rsum0;
        rs[kh * 128 + 16 * qw + r4 + 8] = rsum1;
    }
    // kh=1 warps dump out-partials into scratch (aliases buf0, dead now)
    float* red = (float*)(smem + SM_BUF0);
    if (kh == 1) {
        #pragma unroll
        for (int n = 0; n < 8; ++n) {
            int col = 8 * n + 2 * q4;
            *(float2*)(red + (16 * qw + r4) * 64 + col)       = make_float2(oacc[n][0], oacc[n][1]);
            *(float2*)(red + (16 * qw + r4 + 8) * 64 + col)   = make_float2(oacc[n][2], oacc[n][3]);
        }
    }
    __syncthreads();

    // ---- kh=0 warps: combine halves, normalize, write out ----
    if (kh == 0) {
        int row0 = 16 * qw + r4, row1 = row0 + 8;
        float rinv0 = 1.0f / (rs[row0] + rs[128 + row0]);
        float rinv1 = 1.0f / (rs[row1] + rs[128 + row1]);
        float* orow = out + (bhrow + row0) * DD;
        #pragma unroll
        for (int n = 0; n < 8; ++n) {
            int col = 8 * n + 2 * q4;
            float2 a = *(float2*)(red + row0 * 64 + col);
            float2 c2 = *(float2*)(red + row1 * 64 + col);
            *(float2*)(orow + col)          = make_float2((oacc[n][0] + a.x) * rinv0, (oacc[n][1] + a.y) * rinv0);
            *(float2*)(orow + 8 * DD + col) = make_float2((oacc[n][2] + c2.x) * rinv1, (oacc[n][3] + c2.y) * rinv1);
        }
    }
    __syncthreads();

    // ---- normalize probs (block's own 1MB slice; mostly L2-hot) ----
    {
        int rown = tid >> 2, qtr = tid & 3;
        float ri = 1.0f / (rs[rown] + rs[128 + rown]);
        float* pr = probs + (bhrow + rown) * SS + qtr * (SS / 4);
        #pragma unroll 4
        for (int i = 0; i < (SS / 4) / 4; ++i) {
            float4 t = *(float4*)(pr + 4 * i);
            t.x *= ri; t.y *= ri; t.z *= ri; t.w *= ri;
            *(float4*)(pr + 4 * i) = t;
        }
    }
}

extern "C" void kernel_launch(void* const* d_in, const int* in_sizes, int n_in,
                              void* d_out, int out_size)
{
    const float* q    = (const float*)d_in[0];
    const float* k    = (const float*)d_in[1];
    const float* v    = (const float*)d_in[2];
    const int*   mask = (const int*)d_in[3];

    float* out   = (float*)d_out;
    float* probs = (float*)d_out + (size_t)BB * HH * SS * DD;

    cudaFuncSetAttribute(attn_hmma2_kernel,
                         cudaFuncAttributeMaxDynamicSharedMemorySize, SM_TOTAL);

    dim3 grid(SS / MT, BB * HH);   // (16, 24) = 384 blocks
    attn_hmma2_kernel<<<grid, THREADS, SM_TOTAL>>>(q, k, v, mask, out, probs);
}

// round 6
// speedup vs baseline: 1.1821x; 1.1821x over previous
#include <cuda_runtime.h>
#include <cuda_bf16.h>
#include <cstdint>
#include <cstddef>

#define BB 2
#define HH 12
#define SS 2048
#define DD 64
#define MT 128
#define NK 128
#define NCH (SS/NK)         // 16
#define THREADS 512

// per-(bh,chunk) 64KB block: KHI|KLO|VHI|VLO (each 16KB, swizzled smem image)
__device__ __align__(16) unsigned char g_kvbuf[(size_t)BB * HH * NCH * 65536];

// ---- smem ----
#define SM_BUFSZ 65536
#define SM_BM    131072               // 2 x 4 uint32 bitmasks
#define SM_RS    131104               // 2 x 128 floats
#define SM_TOTAL 132160

__device__ __forceinline__ uint32_t smem_u32(const void* p) {
    uint32_t a;
    asm("{ .reg .u64 t; cvta.to.shared.u64 t, %1; cvt.u32.u64 %0, t; }" : "=r"(a) : "l"(p));
    return a;
}
__device__ __forceinline__ uint32_t swz(int row, int ch) {
    return (uint32_t)(row * 128 + ((ch ^ (row & 7)) << 4));
}
__device__ __forceinline__ void ldmx4(uint32_t* r, uint32_t addr) {
    asm volatile("ldmatrix.sync.aligned.m8n8.x4.shared.b16 {%0,%1,%2,%3}, [%4];"
                 : "=r"(r[0]), "=r"(r[1]), "=r"(r[2]), "=r"(r[3]) : "r"(addr));
}
__device__ __forceinline__ void ldmx4t(uint32_t* r, uint32_t addr) {
    asm volatile("ldmatrix.sync.aligned.m8n8.x4.trans.shared.b16 {%0,%1,%2,%3}, [%4];"
                 : "=r"(r[0]), "=r"(r[1]), "=r"(r[2]), "=r"(r[3]) : "r"(addr));
}
__device__ __forceinline__ void mma16816(float* d, const uint32_t* a, const uint32_t* b) {
    asm volatile("mma.sync.aligned.m16n8k16.row.col.f32.bf16.bf16.f32 "
                 "{%0,%1,%2,%3}, {%4,%5,%6,%7}, {%8,%9}, {%0,%1,%2,%3};"
                 : "+f"(d[0]), "+f"(d[1]), "+f"(d[2]), "+f"(d[3])
                 : "r"(a[0]), "r"(a[1]), "r"(a[2]), "r"(a[3]), "r"(b[0]), "r"(b[1]));
}
__device__ __forceinline__ void cvt_split(float a, float b, uint32_t& hw, uint32_t& lw) {
    __nv_bfloat16 ha = __float2bfloat16(a), hb = __float2bfloat16(b);
    float ra = a - __bfloat162float(ha);
    float rb = b - __bfloat162float(hb);
    hw = ((uint32_t)__bfloat16_as_ushort(hb) << 16) | (uint32_t)__bfloat16_as_ushort(ha);
    __nv_bfloat16 la = __float2bfloat16(ra), lb = __float2bfloat16(rb);
    lw = ((uint32_t)__bfloat16_as_ushort(lb) << 16) | (uint32_t)__bfloat16_as_ushort(la);
}
#define CP16(dst, src) asm volatile("cp.async.cg.shared.global [%0], [%1], 16;" :: "r"(dst), "l"(src))
#define CP_COMMIT()    asm volatile("cp.async.commit_group;" ::: "memory")

extern __shared__ char smem[];

// ============ aux kernel: K/V fp32 -> swizzled bf16 hi/lo global image ============
__global__ __launch_bounds__(256, 4)
void conv_kv_kernel(const float* __restrict__ k, const float* __restrict__ v)
{
    const int bh = blockIdx.x, c = blockIdx.y, tid = threadIdx.x;
    const float* ks = k + ((size_t)bh * SS + c * NK) * DD;
    const float* vs = v + ((size_t)bh * SS + c * NK) * DD;
    unsigned char* dst = g_kvbuf + ((size_t)(bh * NCH + c) << 16);
    #pragma unroll
    for (int it = 0; it < 16; ++it) {
        int lin = it * 256 + tid;
        int rr = lin >> 5, dp = lin & 31;
        uint32_t off = (uint32_t)(rr * 128) + (((dp >> 2) ^ (rr & 7)) << 4) + ((dp & 3) << 2);
        float2 tk = *(const float2*)(ks + rr * DD + 2 * dp);
        uint32_t hw, lw;
        cvt_split(tk.x, tk.y, hw, lw);
        *(uint32_t*)(dst + off)         = hw;
        *(uint32_t*)(dst + 16384 + off) = lw;
        float2 tv = *(const float2*)(vs + rr * DD + 2 * dp);
        cvt_split(tv.x, tv.y, hw, lw);
        *(uint32_t*)(dst + 32768 + off) = hw;
        *(uint32_t*)(dst + 49152 + off) = lw;
    }
}

// ============ main attention kernel ============
__global__ __launch_bounds__(THREADS, 1)
void attn_hmma3_kernel(const float* __restrict__ q,
                       const int*   __restrict__ mask,
                       float* __restrict__ out,
                       float* __restrict__ probs)
{
    const uint32_t sbase = smem_u32(smem);
    const int tid = threadIdx.x;
    const int wid = tid >> 5;
    const int lid = tid & 31;
    const int qw  = wid >> 1;        // q-row tile 0..7
    const int kh  = wid & 1;         // key half (0: keys 0-63, 1: 64-127)
    const int grp = lid >> 3;
    const int lr  = lid & 7;
    const int q4  = lid & 3;
    const int r4  = lid >> 2;

    const int bh = blockIdx.y;
    const int b  = bh / HH;
    const int q0 = blockIdx.x * MT;
    const size_t bhrow = (size_t)bh * SS + q0;

    const float* qptr = q + bhrow * DD;
    const int*   mbase = mask + b * SS;
    const unsigned char* gsrc = g_kvbuf + ((size_t)bh * NCH << 16);
    uint32_t* BMp = (uint32_t*)(smem + SM_BM);
    float*    rs  = (float*)(smem + SM_RS);

    // ---- stage Q (x0.125) into buf0 K region, load A-fragments ----
    #pragma unroll
    for (int it = 0; it < 8; ++it) {
        int lin = it * THREADS + tid;
        int rr = lin >> 5, dp = lin & 31;
        float2 t = *(const float2*)(qptr + rr * DD + 2 * dp);
        uint32_t hw, lw;
        cvt_split(t.x * 0.125f, t.y * 0.125f, hw, lw);
        uint32_t off = (uint32_t)(rr * 128) + (((dp >> 2) ^ (rr & 7)) << 4) + ((dp & 3) << 2);
        *(uint32_t*)(smem + off)         = hw;
        *(uint32_t*)(smem + 16384 + off) = lw;
    }
    if (tid < NK) {
        uint32_t bal = __ballot_sync(0xFFFFFFFFu, mbase[tid] != 0);
        if ((tid & 31) == 0) BMp[tid >> 5] = bal;
    }
    __syncthreads();
    uint32_t qh[4][4], ql[4][4];
    {
        int row = 16 * qw + ((grp & 1) << 3) + lr;
        #pragma unroll
        for (int cc = 0; cc < 4; ++cc) {
            int ch = 2 * cc + (grp >> 1);
            ldmx4(qh[cc], sbase + swz(row, ch));
            ldmx4(ql[cc], sbase + 16384 + swz(row, ch));
        }
    }
    __syncthreads();   // Q frag reads done before cp.async overwrites buf0

    // ---- prologue: async-load chunk 0 into buf0 ----
    {
        const unsigned char* src = gsrc + tid * 128;
        uint32_t dst = sbase + tid * 128;
        #pragma unroll
        for (int i = 0; i < 8; ++i) CP16(dst + 16 * i, src + 16 * i);
        CP_COMMIT();
    }

    float oacc[8][4];
    #pragma unroll
    for (int n = 0; n < 8; ++n)
        #pragma unroll
        for (int i = 0; i < 4; ++i) oacc[n][i] = 0.0f;
    float rsum0 = 0.0f, rsum1 = 0.0f;

    for (int c = 0; c < NCH; ++c) {
        const uint32_t bufb = sbase + (uint32_t)(c & 1) * SM_BUFSZ;
        const bool more = (c + 1 < NCH);

        // issue next chunk's async copy + mask bitmask
        if (more) {
            const unsigned char* src = gsrc + ((size_t)(c + 1) << 16) + tid * 128;
            uint32_t dst = sbase + (uint32_t)((c + 1) & 1) * SM_BUFSZ + tid * 128;
            #pragma unroll
            for (int i = 0; i < 8; ++i) CP16(dst + 16 * i, src + 16 * i);
            CP_COMMIT();
            if (tid < NK) {
                uint32_t bal = __ballot_sync(0xFFFFFFFFu, mbase[(c + 1) * NK + tid] != 0);
                if ((tid & 31) == 0) BMp[((c + 1) & 1) * 4 + (tid >> 5)] = bal;
            }
            asm volatile("cp.async.wait_group 1;" ::: "memory");
        } else {
            asm volatile("cp.async.wait_group 0;" ::: "memory");
        }
        __syncthreads();   // chunk c data visible to all warps

        // ---- QK^T: S[16 x 64] per warp, hi/lo split ----
        float sc[8][4];
        #pragma unroll
        for (int t = 0; t < 8; ++t)
            #pragma unroll
            for (int i = 0; i < 4; ++i) sc[t][i] = 0.0f;

        #pragma unroll
        for (int np = 0; np < 4; ++np) {
            int krow = kh * 64 + 16 * np + ((grp >> 1) << 3) + lr;
            #pragma unroll
            for (int cc = 0; cc < 4; ++cc) {
                int ch = 2 * cc + (grp & 1);
                uint32_t bhv[4], blv[4];
                ldmx4(bhv, bufb + swz(krow, ch));
                ldmx4(blv, bufb + 16384 + swz(krow, ch));
                mma16816(sc[2*np],   qh[cc], bhv + 0);
                mma16816(sc[2*np],   qh[cc], blv + 0);
                mma16816(sc[2*np],   ql[cc], bhv + 0);
                mma16816(sc[2*np+1], qh[cc], bhv + 2);
                mma16816(sc[2*np+1], qh[cc], blv + 2);
                mma16816(sc[2*np+1], ql[cc], bhv + 2);
            }
        }

        // ---- epilogue: mask + exp, probs store, rowsum, pack A-frags ----
        const uint32_t bm0 = BMp[(c & 1) * 4 + kh * 2];
        const uint32_t bm1 = BMp[(c & 1) * 4 + kh * 2 + 1];
        float* prow = probs + (bhrow + 16 * qw + r4) * SS + c * NK + kh * 64;
        #pragma unroll
        for (int t = 0; t < 8; ++t) {
            int kl = 8 * t + 2 * q4;
            uint32_t bmw = (t < 4) ? bm0 : bm1;
            int sh = kl & 31;
            float p0 = ((bmw >> sh) & 1u)       ? __expf(sc[t][0]) : 0.0f;
            float p1 = ((bmw >> (sh + 1)) & 1u) ? __expf(sc[t][1]) : 0.0f;
            float p2 = ((bmw >> sh) & 1u)       ? __expf(sc[t][2]) : 0.0f;
            float p3 = ((bmw >> (sh + 1)) & 1u) ? __expf(sc[t][3]) : 0.0f;
            rsum0 += p0 + p1; rsum1 += p2 + p3;
            *(float2*)(prow + kl)          = make_float2(p0, p1);
            *(float2*)(prow + 8 * SS + kl) = make_float2(p2, p3);
            sc[t][0] = p0; sc[t][1] = p1; sc[t][2] = p2; sc[t][3] = p3;
        }
        uint32_t ahi[4][4], alo[4][4];
        #pragma unroll
        for (int j = 0; j < 4; ++j) {
            cvt_split(sc[2*j][0],   sc[2*j][1],   ahi[j][0], alo[j][0]);
            cvt_split(sc[2*j][2],   sc[2*j][3],   ahi[j][1], alo[j][1]);
            cvt_split(sc[2*j+1][0], sc[2*j+1][1], ahi[j][2], alo[j][2]);
            cvt_split(sc[2*j+1][2], sc[2*j+1][3], ahi[j][3], alo[j][3]);
        }

        // ---- PV: out[16 x 64] += P(kh half) . V, hi/lo split ----
        #pragma unroll
        for (int np = 0; np < 4; ++np) {
            int ch = 2 * np + (grp >> 1);
            #pragma unroll
            for (int j = 0; j < 4; ++j) {
                int vrow = kh * 64 + 16 * j + ((grp & 1) << 3) + lr;
                uint32_t vh[4], vl[4];
                ldmx4t(vh, bufb + 32768 + swz(vrow, ch));
                ldmx4t(vl, bufb + 49152 + swz(vrow, ch));
                mma16816(oacc[2*np],   ahi[j], vh + 0);
                mma16816(oacc[2*np],   ahi[j], vl + 0);
                mma16816(oacc[2*np],   alo[j], vh + 0);
                mma16816(oacc[2*np+1], ahi[j], vh + 2);
                mma16816(oacc[2*np+1], ahi[j], vl + 2);
                mma16816(oacc[2*np+1], alo[j], vh + 2);
            }
        }
        __syncthreads();   // reads of buf c done before next overwrite
    }

    // ---- rowsums, cross-half combine, write out ----
    rsum0 += __shfl_xor_sync(0xFFFFFFFFu, rsum0, 1);
    rsum0 += __shfl_xor_sync(0xFFFFFFFFu, rsum0, 2);
    rsum1 += __shfl_xor_sync(0xFFFFFFFFu, rsum1, 1);
    rsum1 += __shfl_xor_sync(0xFFFFFFFFu, rsum1, 2);
    if (q4 == 0) {
        rs[kh * 128 + 16 * qw + r4]     = rsum0;
        rs[kh * 128 + 16 * qw + r4 + 8] = rsum1;
    }
    float* red = (float*)smem;   // aliases buf0 (dead)
    if (kh == 1) {
        #pragma unroll
        for (int n = 0; n < 8; ++n) {
            int col = 8 * n + 2 * q4;
            *(float2*)(red + (16 * qw + r4) * 64 + col)     = make_float2(oacc[n][0], oacc[n][1]);
            *(float2*)(red + (16 * qw + r4 + 8) * 64 + col) = make_float2(oacc[n][2], oacc[n][3]);
        }
    }
    __syncthreads();
    if (kh == 0) {
        int row0 = 16 * qw + r4, row1 = row0 + 8;
        float rinv0 = 1.0f / (rs[row0] + rs[128 + row0]);
        float rinv1 = 1.0f / (rs[row1] + rs[128 + row1]);
        float* orow = out + (bhrow + row0) * DD;
        #pragma unroll
        for (int n = 0; n < 8; ++n) {
            int col = 8 * n + 2 * q4;
            float2 a  = *(float2*)(red + row0 * 64 + col);
            float2 c2 = *(float2*)(red + row1 * 64 + col);
            *(float2*)(orow + col)          = make_float2((oacc[n][0] + a.x) * rinv0, (oacc[n][1] + a.y) * rinv0);
            *(float2*)(orow + 8 * DD + col) = make_float2((oacc[n][2] + c2.x) * rinv1, (oacc[n][3] + c2.y) * rinv1);
        }
    }
    __syncthreads();

    // ---- normalize probs: warp-per-rows, fully coalesced 512B/instr ----
    {
        #pragma unroll
        for (int r = 0; r < 8; ++r) {
            int row = wid * 8 + r;
            float ri = 1.0f / (rs[row] + rs[128 + row]);
            float* pr = probs + (bhrow + row) * SS;
            #pragma unroll 4
            for (int i = 0; i < SS / 128; ++i) {
                float4 t = *(float4*)(pr + (i * 32 + lid) * 4);
                t.x *= ri; t.y *= ri; t.z *= ri; t.w *= ri;
                *(float4*)(pr + (i * 32 + lid) * 4) = t;
            }
        }
    }
}

extern "C" void kernel_launch(void* const* d_in, const int* in_sizes, int n_in,
                              void* d_out, int out_size)
{
    const float* q    = (const float*)d_in[0];
    const float* k    = (const float*)d_in[1];
    const float* v    = (const float*)d_in[2];
    const int*   mask = (const int*)d_in[3];

    float* out   = (float*)d_out;
    float* probs = (float*)d_out + (size_t)BB * HH * SS * DD;

    dim3 cgrid(BB * HH, NCH);
    conv_kv_kernel<<<cgrid, 256>>>(k, v);

    cudaFuncSetAttribute(attn_hmma3_kernel,
                         cudaFuncAttributeMaxDynamicSharedMemorySize, SM_TOTAL);
    dim3 grid(SS / MT, BB * HH);   // (16, 24)
    attn_hmma3_kernel<<<grid, THREADS, SM_TOTAL>>>(q, mask, out, probs);
}

// round 8
// speedup vs baseline: 1.3124x; 1.1103x over previous
#include <cuda_runtime.h>
#include <cuda_bf16.h>
#include <cstdint>
#include <cstddef>

#define BB 2
#define HH 12
#define SS 2048
#define DD 64
#define MT 128
#define NK 128
#define NCH (SS/NK)         // 16
#define THREADS 512

// per-(bh,chunk) 64KB block: KHI|KLO|VHI|VLO (each 16KB, swizzled smem image)
__device__ __align__(16) unsigned char g_kvbuf[(size_t)BB * HH * NCH * 65536];

// ---- smem layout ----
#define SM_BUFSZ 65536                // buf0 @0, buf1 @65536
#define SM_Q     131072               // QHI @+0, QLO @+16384 (32KB, persistent)
#define SM_BM    163840               // 2 x 4 uint32 bitmasks
#define SM_RS    163904               // 2 x 128 floats
#define SM_TOTAL 164992

__device__ __forceinline__ uint32_t smem_u32(const void* p) {
    uint32_t a;
    asm("{ .reg .u64 t; cvta.to.shared.u64 t, %1; cvt.u32.u64 %0, t; }" : "=r"(a) : "l"(p));
    return a;
}
__device__ __forceinline__ uint32_t swz(int row, int ch) {
    return (uint32_t)(row * 128 + ((ch ^ (row & 7)) << 4));
}
__device__ __forceinline__ void ldmx4(uint32_t* r, uint32_t addr) {
    asm volatile("ldmatrix.sync.aligned.m8n8.x4.shared.b16 {%0,%1,%2,%3}, [%4];"
                 : "=r"(r[0]), "=r"(r[1]), "=r"(r[2]), "=r"(r[3]) : "r"(addr));
}
__device__ __forceinline__ void ldmx4t(uint32_t* r, uint32_t addr) {
    asm volatile("ldmatrix.sync.aligned.m8n8.x4.trans.shared.b16 {%0,%1,%2,%3}, [%4];"
                 : "=r"(r[0]), "=r"(r[1]), "=r"(r[2]), "=r"(r[3]) : "r"(addr));
}
__device__ __forceinline__ void mma16816(float* d, const uint32_t* a, const uint32_t* b) {
    asm volatile("mma.sync.aligned.m16n8k16.row.col.f32.bf16.bf16.f32 "
                 "{%0,%1,%2,%3}, {%4,%5,%6,%7}, {%8,%9}, {%0,%1,%2,%3};"
                 : "+f"(d[0]), "+f"(d[1]), "+f"(d[2]), "+f"(d[3])
                 : "r"(a[0]), "r"(a[1]), "r"(a[2]), "r"(a[3]), "r"(b[0]), "r"(b[1]));
}
__device__ __forceinline__ void cvt_split(float a, float b, uint32_t& hw, uint32_t& lw) {
    __nv_bfloat16 ha = __float2bfloat16(a), hb = __float2bfloat16(b);
    float ra = a - __bfloat162float(ha);
    float rb = b - __bfloat162float(hb);
    hw = ((uint32_t)__bfloat16_as_ushort(hb) << 16) | (uint32_t)__bfloat16_as_ushort(ha);
    __nv_bfloat16 la = __float2bfloat16(ra), lb = __float2bfloat16(rb);
    lw = ((uint32_t)__bfloat16_as_ushort(lb) << 16) | (uint32_t)__bfloat16_as_ushort(la);
}
#define CP16(dst, src) asm volatile("cp.async.cg.shared.global [%0], [%1], 16;" :: "r"(dst), "l"(src))
#define CP_COMMIT()    asm volatile("cp.async.commit_group;" ::: "memory")

extern __shared__ char smem[];

// ============ aux kernel: K/V fp32 -> swizzled bf16 hi/lo global image ============
__global__ __launch_bounds__(256, 4)
void conv_kv_kernel(const float* __restrict__ k, const float* __restrict__ v)
{
    const int bh = blockIdx.x, c = blockIdx.y, tid = threadIdx.x;
    const float* ks = k + ((size_t)bh * SS + c * NK) * DD;
    const float* vs = v + ((size_t)bh * SS + c * NK) * DD;
    unsigned char* dst = g_kvbuf + ((size_t)(bh * NCH + c) << 16);
    #pragma unroll
    for (int it = 0; it < 16; ++it) {
        int lin = it * 256 + tid;
        int rr = lin >> 5, dp = lin & 31;
        uint32_t off = (uint32_t)(rr * 128) + (((dp >> 2) ^ (rr & 7)) << 4) + ((dp & 3) << 2);
        float2 tk = *(const float2*)(ks + rr * DD + 2 * dp);
        uint32_t hw, lw;
        cvt_split(tk.x, tk.y, hw, lw);
        *(uint32_t*)(dst + off)         = hw;
        *(uint32_t*)(dst + 16384 + off) = lw;
        float2 tv = *(const float2*)(vs + rr * DD + 2 * dp);
        cvt_split(tv.x, tv.y, hw, lw);
        *(uint32_t*)(dst + 32768 + off) = hw;
        *(uint32_t*)(dst + 49152 + off) = lw;
    }
}

// ============ main attention kernel ============
__global__ __launch_bounds__(THREADS, 1)
void attn_hmma4_kernel(const float* __restrict__ q,
                       const int*   __restrict__ mask,
                       float* __restrict__ out,
                       float* __restrict__ probs)
{
    const uint32_t sbase = smem_u32(smem);
    const int tid = threadIdx.x;
    const int wid = tid >> 5;
    const int lid = tid & 31;
    const int qw  = wid >> 1;        // q-row tile 0..7
    const int kh  = wid & 1;         // key half (0: keys 0-63, 1: 64-127)
    const int grp = lid >> 3;
    const int lr  = lid & 7;
    const int q4  = lid & 3;
    const int r4  = lid >> 2;

    const int bh = blockIdx.y;
    const int b  = bh / HH;
    const int q0 = blockIdx.x * MT;
    const size_t bhrow = (size_t)bh * SS + q0;

    const float* qptr = q + bhrow * DD;
    const int*   mbase = mask + b * SS;
    const unsigned char* gsrc = g_kvbuf + ((size_t)bh * NCH << 16);
    uint32_t* BMp = (uint32_t*)(smem + SM_BM);
    float*    rs  = (float*)(smem + SM_RS);

    // ---- stage Q (x0.125) hi/lo into persistent SM_Q region ----
    #pragma unroll
    for (int it = 0; it < 8; ++it) {
        int lin = it * THREADS + tid;
        int rr = lin >> 5, dp = lin & 31;
        float2 t = *(const float2*)(qptr + rr * DD + 2 * dp);
        uint32_t hw, lw;
        cvt_split(t.x * 0.125f, t.y * 0.125f, hw, lw);
        uint32_t off = (uint32_t)(rr * 128) + (((dp >> 2) ^ (rr & 7)) << 4) + ((dp & 3) << 2);
        *(uint32_t*)(smem + SM_Q + off)         = hw;
        *(uint32_t*)(smem + SM_Q + 16384 + off) = lw;
    }
    if (tid < NK) {
        uint32_t bal = __ballot_sync(0xFFFFFFFFu, mbase[tid] != 0);
        if ((tid & 31) == 0) BMp[tid >> 5] = bal;
    }
    // ---- prologue: async-load chunk 0 into buf0 ----
    {
        const unsigned char* src = gsrc + tid * 128;
        uint32_t dst = sbase + tid * 128;
        #pragma unroll
        for (int i = 0; i < 8; ++i) CP16(dst + 16 * i, src + 16 * i);
        CP_COMMIT();
    }

    float oacc[8][4];
    #pragma unroll
    for (int n = 0; n < 8; ++n)
        #pragma unroll
        for (int i = 0; i < 4; ++i) oacc[n][i] = 0.0f;
    float rsum0 = 0.0f, rsum1 = 0.0f;

    const int qrow = 16 * qw + ((grp & 1) << 3) + lr;   // Q fragment row
    const int chq_add = grp >> 1;                        // Q fragment ch offset

    for (int c = 0; c < NCH; ++c) {
        const uint32_t bufb = sbase + (uint32_t)(c & 1) * SM_BUFSZ;
        const bool more = (c + 1 < NCH);

        if (more) {
            const unsigned char* src = gsrc + ((size_t)(c + 1) << 16) + tid * 128;
            uint32_t dst = sbase + (uint32_t)((c + 1) & 1) * SM_BUFSZ + tid * 128;
            #pragma unroll
            for (int i = 0; i < 8; ++i) CP16(dst + 16 * i, src + 16 * i);
            CP_COMMIT();
            if (tid < NK) {
                uint32_t bal = __ballot_sync(0xFFFFFFFFu, mbase[(c + 1) * NK + tid] != 0);
                if ((tid & 31) == 0) BMp[((c + 1) & 1) * 4 + (tid >> 5)] = bal;
            }
            asm volatile("cp.async.wait_group 1;" ::: "memory");
        } else {
            asm volatile("cp.async.wait_group 0;" ::: "memory");
        }
        __syncthreads();

        // ---- QK^T: S[16 x 64] per warp, hi/lo split; Q frags reloaded per cc ----
        float sc[8][4];
        #pragma unroll
        for (int t = 0; t < 8; ++t)
            #pragma unroll
            for (int i = 0; i < 4; ++i) sc[t][i] = 0.0f;

        #pragma unroll
        for (int cc = 0; cc < 4; ++cc) {
            uint32_t qhf[4], qlf[4];
            int chq = 2 * cc + chq_add;
            ldmx4(qhf, sbase + SM_Q + swz(qrow, chq));
            ldmx4(qlf, sbase + SM_Q + 16384 + swz(qrow, chq));
            int ch = 2 * cc + (grp & 1);
            #pragma unroll
            for (int np = 0; np < 4; ++np) {
                int krow = kh * 64 + 16 * np + ((grp >> 1) << 3) + lr;
                uint32_t bhv[4], blv[4];
                ldmx4(bhv, bufb + swz(krow, ch));
                ldmx4(blv, bufb + 16384 + swz(krow, ch));
                mma16816(sc[2*np],   qhf, bhv + 0);
                mma16816(sc[2*np],   qhf, blv + 0);
                mma16816(sc[2*np],   qlf, bhv + 0);
                mma16816(sc[2*np+1], qhf, bhv + 2);
                mma16816(sc[2*np+1], qhf, blv + 2);
                mma16816(sc[2*np+1], qlf, bhv + 2);
            }
        }

        // ---- epilogue: mask + exp, probs store, rowsum (p kept in sc) ----
        const uint32_t bm0 = BMp[(c & 1) * 4 + kh * 2];
        const uint32_t bm1 = BMp[(c & 1) * 4 + kh * 2 + 1];
        float* prow = probs + (bhrow + 16 * qw + r4) * SS + c * NK + kh * 64;
        #pragma unroll
        for (int t = 0; t < 8; ++t) {
            int kl = 8 * t + 2 * q4;
            uint32_t bmw = (t < 4) ? bm0 : bm1;
            int sh = kl & 31;
            float p0 = ((bmw >> sh) & 1u)       ? __expf(sc[t][0]) : 0.0f;
            float p1 = ((bmw >> (sh + 1)) & 1u) ? __expf(sc[t][1]) : 0.0f;
            float p2 = ((bmw >> sh) & 1u)       ? __expf(sc[t][2]) : 0.0f;
            float p3 = ((bmw >> (sh + 1)) & 1u) ? __expf(sc[t][3]) : 0.0f;
            rsum0 += p0 + p1; rsum1 += p2 + p3;
            *(float2*)(prow + kl)          = make_float2(p0, p1);
            *(float2*)(prow + 8 * SS + kl) = make_float2(p2, p3);
            sc[t][0] = p0; sc[t][1] = p1; sc[t][2] = p2; sc[t][3] = p3;
        }

        // ---- PV fused with pack: per j, pack 8 regs then 24 mma ----
        #pragma unroll
        for (int j = 0; j < 4; ++j) {
            uint32_t ah[4], al[4];
            cvt_split(sc[2*j][0],   sc[2*j][1],   ah[0], al[0]);
            cvt_split(sc[2*j][2],   sc[2*j][3],   ah[1], al[1]);
            cvt_split(sc[2*j+1][0], sc[2*j+1][1], ah[2], al[2]);
            cvt_split(sc[2*j+1][2], sc[2*j+1][3], ah[3], al[3]);
            int vrow = kh * 64 + 16 * j + ((grp & 1) << 3) + lr;
            #pragma unroll
            for (int np = 0; np < 4; ++np) {
                int ch = 2 * np + (grp >> 1);
                uint32_t vh[4], vl[4];
                ldmx4t(vh, bufb + 32768 + swz(vrow, ch));
                ldmx4t(vl, bufb + 49152 + swz(vrow, ch));
                mma16816(oacc[2*np],   ah, vh + 0);
                mma16816(oacc[2*np],   ah, vl + 0);
                mma16816(oacc[2*np],   al, vh + 0);
                mma16816(oacc[2*np+1], ah, vh + 2);
                mma16816(oacc[2*np+1], ah, vl + 2);
                mma16816(oacc[2*np+1], al, vh + 2);
            }
        }
        __syncthreads();   // reads of buf c done before next overwrite
    }

    // ---- rowsums, cross-half combine, write out ----
    rsum0 += __shfl_xor_sync(0xFFFFFFFFu, rsum0, 1);
    rsum0 += __shfl_xor_sync(0xFFFFFFFFu, rsum0, 2);
    rsum1 += __shfl_xor_sync(0xFFFFFFFFu, rsum1, 1);
    rsum1 += __shfl_xor_sync(0xFFFFFFFFu, rsum1, 2);
    if (q4 == 0) {
        rs[kh * 128 + 16 * qw + r4]     = rsum0;
        rs[kh * 128 + 16 * qw + r4 + 8] = rsum1;
    }
    float* red = (float*)smem;   // aliases buf0 (dead)
    if (kh == 1) {
        #pragma unroll
        for (int n = 0; n < 8; ++n) {
            int col = 8 * n + 2 * q4;
            *(float2*)(red + (16 * qw + r4) * 64 + col)     = make_float2(oacc[n][0], oacc[n][1]);
            *(float2*)(red + (16 * qw + r4 + 8) * 64 + col) = make_float2(oacc[n][2], oacc[n][3]);
        }
    }
    __syncthreads();
    if (kh == 0) {
        int row0 = 16 * qw + r4, row1 = row0 + 8;
        float rinv0 = 1.0f / (rs[row0] + rs[128 + row0]);
        float rinv1 = 1.0f / (rs[row1] + rs[128 + row1]);
        float* orow = out + (bhrow + row0) * DD;
        #pragma unroll
        for (int n = 0; n < 8; ++n) {
            int col = 8 * n + 2 * q4;
            float2 a  = *(float2*)(red + row0 * 64 + col);
            float2 c2 = *(float2*)(red + row1 * 64 + col);
            *(float2*)(orow + col)          = make_float2((oacc[n][0] + a.x) * rinv0, (oacc[n][1] + a.y) * rinv0);
            *(float2*)(orow + 8 * DD + col) = make_float2((oacc[n][2] + c2.x) * rinv1, (oacc[n][3] + c2.y) * rinv1);
        }
    }
    __syncthreads();

    // ---- normalize probs: warp-per-rows, fully coalesced ----
    {
        #pragma unroll
        for (int r = 0; r < 8; ++r) {
            int row = wid * 8 + r;
            float ri = 1.0f / (rs[row] + rs[128 + row]);
            float* pr = probs + (bhrow + row) * SS;
            #pragma unroll 4
            for (int i = 0; i < SS / 128; ++i) {
                float4 t = *(float4*)(pr + (i * 32 + lid) * 4);
                t.x *= ri; t.y *= ri; t.z *= ri; t.w *= ri;
                *(float4*)(pr + (i * 32 + lid) * 4) = t;
            }
        }
    }
}

extern "C" void kernel_launch(void* const* d_in, const int* in_sizes, int n_in,
                              void* d_out, int out_size)
{
    const float* q    = (const float*)d_in[0];
    const float* k    = (const float*)d_in[1];
    const float* v    = (const float*)d_in[2];
    const int*   mask = (const int*)d_in[3];

    float* out   = (float*)d_out;
    float* probs = (float*)d_out + (size_t)BB * HH * SS * DD;

    dim3 cgrid(BB * HH, NCH);
    conv_kv_kernel<<<cgrid, 256>>>(k, v);

    cudaFuncSetAttribute(attn_hmma4_kernel,
                         cudaFuncAttributeMaxDynamicSharedMemorySize, SM_TOTAL);
    dim3 grid(SS / MT, BB * HH);   // (16, 24)
    attn_hmma4_kernel<<<grid, THREADS, SM_TOTAL>>>(q, mask, out, probs);
}